// round 12
// baseline (speedup 1.0000x reference)
#include <cuda_runtime.h>
#include <math.h>
#include <stdint.h>

#define BB      8
#define LSEQ    4096
#define DIMC    384
#define NDEPTH  6
#define NSTATE  16
#define NCONV   4
#define DINNER  768
#define DTRANK  24
#define HIDF    768
#define MTOK    (BB*LSEQ)             // 32768
#define DBLW    (DTRANK + 2*NSTATE)   // 56

// ---------------- scratch (static device globals; no allocation) ----------------
__device__ float g_x  [MTOK*DIMC];
__device__ float g_xn [MTOK*DIMC];
__device__ float g_xz [MTOK*2*DINNER];
__device__ float g_xi [MTOK*DINNER];
__device__ float g_dbl[MTOK*DBLW];
__device__ float g_dt [MTOK*DINNER];
__device__ float g_y  [MTOK*DINNER];

// ---------------- math helpers ----------------
__device__ __forceinline__ float siluf(float v) {
    return v / (1.0f + expf(-v));
}
__device__ __forceinline__ float softplusf(float v) {
    return (v >= 0.0f) ? (v + log1pf(expf(-v))) : log1pf(expf(v));
}
__device__ __forceinline__ float geluf(float v) {
    float c = 0.7978845608028654f * (v + 0.044715f * v * v * v);
    return 0.5f * v * (1.0f + tanhf(c));
}

// ---------------- elementwise: x = x + pos_emb ----------------
__global__ void add_pos_kernel(const float* __restrict__ x,
                               const float* __restrict__ pos,
                               float* __restrict__ out) {
    int idx = blockIdx.x * blockDim.x + threadIdx.x;
    if (idx >= MTOK * DIMC / 4) return;
    int m  = idx / (DIMC / 4);
    int c4 = idx % (DIMC / 4);
    int l  = m & (LSEQ - 1);
    float4 xv = ((const float4*)x)[idx];
    float4 pv = ((const float4*)pos)[l * (DIMC / 4) + c4];
    xv.x += pv.x; xv.y += pv.y; xv.z += pv.z; xv.w += pv.w;
    ((float4*)out)[idx] = xv;
}

// ---------------- layernorm over DIMC=384 (one warp per token) ----------------
__global__ void ln_kernel(const float* __restrict__ x, float* __restrict__ o,
                          const float* __restrict__ s, const float* __restrict__ bb) {
    int gwarp = (blockIdx.x * blockDim.x + threadIdx.x) >> 5;
    int lane  = threadIdx.x & 31;
    if (gwarp >= MTOK) return;
    const float* xp = x + (size_t)gwarp * DIMC;
    float4 v0 = *(const float4*)(xp + lane * 4);
    float4 v1 = *(const float4*)(xp + 128 + lane * 4);
    float4 v2 = *(const float4*)(xp + 256 + lane * 4);
    float sum = v0.x + v0.y + v0.z + v0.w
              + v1.x + v1.y + v1.z + v1.w
              + v2.x + v2.y + v2.z + v2.w;
    #pragma unroll
    for (int off = 16; off >= 1; off >>= 1) sum += __shfl_xor_sync(0xffffffffu, sum, off);
    float mean = sum * (1.0f / DIMC);
    float q = 0.0f;
    #define QACC(t) { float d_ = (t) - mean; q = fmaf(d_, d_, q); }
    QACC(v0.x) QACC(v0.y) QACC(v0.z) QACC(v0.w)
    QACC(v1.x) QACC(v1.y) QACC(v1.z) QACC(v1.w)
    QACC(v2.x) QACC(v2.y) QACC(v2.z) QACC(v2.w)
    #undef QACC
    #pragma unroll
    for (int off = 16; off >= 1; off >>= 1) q += __shfl_xor_sync(0xffffffffu, q, off);
    float rstd = rsqrtf(q * (1.0f / DIMC) + 1e-5f);

    float4 s0 = *(const float4*)(s + lane * 4);
    float4 s1 = *(const float4*)(s + 128 + lane * 4);
    float4 s2 = *(const float4*)(s + 256 + lane * 4);
    float4 b0 = *(const float4*)(bb + lane * 4);
    float4 b1 = *(const float4*)(bb + 128 + lane * 4);
    float4 b2 = *(const float4*)(bb + 256 + lane * 4);
    float* op = o + (size_t)gwarp * DIMC;
    float4 r;
    r.x = (v0.x - mean) * rstd * s0.x + b0.x;
    r.y = (v0.y - mean) * rstd * s0.y + b0.y;
    r.z = (v0.z - mean) * rstd * s0.z + b0.z;
    r.w = (v0.w - mean) * rstd * s0.w + b0.w;
    *(float4*)(op + lane * 4) = r;
    r.x = (v1.x - mean) * rstd * s1.x + b1.x;
    r.y = (v1.y - mean) * rstd * s1.y + b1.y;
    r.z = (v1.z - mean) * rstd * s1.z + b1.z;
    r.w = (v1.w - mean) * rstd * s1.w + b1.w;
    *(float4*)(op + 128 + lane * 4) = r;
    r.x = (v2.x - mean) * rstd * s2.x + b2.x;
    r.y = (v2.y - mean) * rstd * s2.y + b2.y;
    r.z = (v2.z - mean) * rstd * s2.z + b2.z;
    r.w = (v2.w - mean) * rstd * s2.w + b2.w;
    *(float4*)(op + 256 + lane * 4) = r;
}

// ============================================================================
// fp32 FFMA TN GEMM, double-buffered smem, BK=16:
//   C[M,N] = A[M,K] @ W[N,K]^T
// Requires M%128==0, N%128==0, K%16==0 (in/out/ff1/ff2 all qualify).
// EPI: 0=store, 2=gelu(v+bias), 3=C+=v, 4=C+=v+bias
// ============================================================================
#define FBM 128
#define FBN 128
#define FBK 16

template <int EPI>
__global__ void __launch_bounds__(256)
fgemm_tn(const float* __restrict__ A, const float* __restrict__ W,
         float* __restrict__ C, const float* __restrict__ bias,
         int M, int N, int K, int lda, int ldw, int ldc) {
    __shared__ __align__(16) float As[2][FBK][FBM + 4];
    __shared__ __align__(16) float Bs[2][FBK][FBN + 4];

    const int m0 = blockIdx.y * FBM;
    const int n0 = blockIdx.x * FBN;
    const int tid = threadIdx.x;
    const int lrow = tid >> 1;          // 0..127
    const int lc   = (tid & 1) * 8;     // 0 or 8
    const int tx = tid & 15, ty = tid >> 4;

    float acc[8][8];
    #pragma unroll
    for (int i = 0; i < 8; i++)
        #pragma unroll
        for (int j = 0; j < 8; j++) acc[i][j] = 0.0f;

    const float* Ap = A + (size_t)(m0 + lrow) * lda;
    const float* Wp = W + (size_t)(n0 + lrow) * ldw;

    // preload tile 0 into registers then buffer 0
    float4 ra0 = *(const float4*)(Ap + lc);
    float4 ra1 = *(const float4*)(Ap + lc + 4);
    float4 rb0 = *(const float4*)(Wp + lc);
    float4 rb1 = *(const float4*)(Wp + lc + 4);

    As[0][lc + 0][lrow] = ra0.x; As[0][lc + 1][lrow] = ra0.y;
    As[0][lc + 2][lrow] = ra0.z; As[0][lc + 3][lrow] = ra0.w;
    As[0][lc + 4][lrow] = ra1.x; As[0][lc + 5][lrow] = ra1.y;
    As[0][lc + 6][lrow] = ra1.z; As[0][lc + 7][lrow] = ra1.w;
    Bs[0][lc + 0][lrow] = rb0.x; Bs[0][lc + 1][lrow] = rb0.y;
    Bs[0][lc + 2][lrow] = rb0.z; Bs[0][lc + 3][lrow] = rb0.w;
    Bs[0][lc + 4][lrow] = rb1.x; Bs[0][lc + 5][lrow] = rb1.y;
    Bs[0][lc + 6][lrow] = rb1.z; Bs[0][lc + 7][lrow] = rb1.w;
    __syncthreads();

    const int nk = K / FBK;
    for (int it = 0; it < nk; it++) {
        const int cur = it & 1, nxt = cur ^ 1;

        // prefetch next tile (global -> registers) while computing on cur
        if (it + 1 < nk) {
            const int kb = (it + 1) * FBK;
            ra0 = *(const float4*)(Ap + kb + lc);
            ra1 = *(const float4*)(Ap + kb + lc + 4);
            rb0 = *(const float4*)(Wp + kb + lc);
            rb1 = *(const float4*)(Wp + kb + lc + 4);
        }

        #pragma unroll
        for (int k = 0; k < FBK; k++) {
            float4 a0 = *(const float4*)&As[cur][k][ty * 4];
            float4 a1 = *(const float4*)&As[cur][k][ty * 4 + 64];
            float4 b0 = *(const float4*)&Bs[cur][k][tx * 4];
            float4 b1 = *(const float4*)&Bs[cur][k][tx * 4 + 64];
            float av[8] = {a0.x, a0.y, a0.z, a0.w, a1.x, a1.y, a1.z, a1.w};
            float bv[8] = {b0.x, b0.y, b0.z, b0.w, b1.x, b1.y, b1.z, b1.w};
            #pragma unroll
            for (int ii = 0; ii < 8; ii++)
                #pragma unroll
                for (int jj = 0; jj < 8; jj++)
                    acc[ii][jj] = fmaf(av[ii], bv[jj], acc[ii][jj]);
        }

        if (it + 1 < nk) {
            As[nxt][lc + 0][lrow] = ra0.x; As[nxt][lc + 1][lrow] = ra0.y;
            As[nxt][lc + 2][lrow] = ra0.z; As[nxt][lc + 3][lrow] = ra0.w;
            As[nxt][lc + 4][lrow] = ra1.x; As[nxt][lc + 5][lrow] = ra1.y;
            As[nxt][lc + 6][lrow] = ra1.z; As[nxt][lc + 7][lrow] = ra1.w;
            Bs[nxt][lc + 0][lrow] = rb0.x; Bs[nxt][lc + 1][lrow] = rb0.y;
            Bs[nxt][lc + 2][lrow] = rb0.z; Bs[nxt][lc + 3][lrow] = rb0.w;
            Bs[nxt][lc + 4][lrow] = rb1.x; Bs[nxt][lc + 5][lrow] = rb1.y;
            Bs[nxt][lc + 6][lrow] = rb1.z; Bs[nxt][lc + 7][lrow] = rb1.w;
        }
        __syncthreads();
    }

    // vectorized epilogue: rows ty*4+{0..3,64..67}, cols n0+tx*4+{0,64}
    #pragma unroll
    for (int ii = 0; ii < 8; ii++) {
        int r = m0 + ty * 4 + ((ii < 4) ? ii : 60 + ii);
        float* crow = C + (size_t)r * ldc;
        #pragma unroll
        for (int half = 0; half < 2; half++) {
            int c = n0 + tx * 4 + half * 64;
            float v0 = acc[ii][half * 4 + 0];
            float v1 = acc[ii][half * 4 + 1];
            float v2 = acc[ii][half * 4 + 2];
            float v3 = acc[ii][half * 4 + 3];
            float4 out;
            if (EPI == 0) {
                out = make_float4(v0, v1, v2, v3);
            } else if (EPI == 2) {
                const float4 bv = *(const float4*)(bias + c);
                out = make_float4(geluf(v0 + bv.x), geluf(v1 + bv.y),
                                  geluf(v2 + bv.z), geluf(v3 + bv.w));
            } else if (EPI == 3) {
                float4 cv = *(const float4*)(crow + c);
                out = make_float4(cv.x + v0, cv.y + v1, cv.z + v2, cv.w + v3);
            } else {
                const float4 bv = *(const float4*)(bias + c);
                float4 cv = *(const float4*)(crow + c);
                out = make_float4(cv.x + v0 + bv.x, cv.y + v1 + bv.y,
                                  cv.z + v2 + bv.z, cv.w + v3 + bv.w);
            }
            *(float4*)(crow + c) = out;
        }
    }
}

// NOTE: fragment layout => acc[ii][half*4+q] maps to column n0 + tx*4 + half*64 + q
// (inner loop consumes bv[] in that order: b0 = cols tx*4.., b1 = cols tx*4+64..)

// ============================================================================
// xproj GEMM: C[M,56] = A[M,768] @ W[56,768]^T — narrow BN=64 tile (single
// n-tile), BK=16 double-buffered, microtile 8x4.
// ============================================================================
__global__ void __launch_bounds__(256)
xgemm_tn(const float* __restrict__ A, const float* __restrict__ W,
         float* __restrict__ C, int M, int K) {
    __shared__ __align__(16) float As[2][FBK][FBM + 4];
    __shared__ __align__(16) float Bs[2][FBK][64 + 4];

    const int m0 = blockIdx.y * FBM;
    const int tid = threadIdx.x;
    const int lrow = tid >> 1;            // A staging: 0..127
    const int lc   = (tid & 1) * 8;
    const int brow = tid >> 2;            // B staging: 0..63
    const int bc   = (tid & 3) * 4;       // 0,4,8,12
    const int tx = tid & 15, ty = tid >> 4;

    float acc[8][4];
    #pragma unroll
    for (int i = 0; i < 8; i++)
        #pragma unroll
        for (int j = 0; j < 4; j++) acc[i][j] = 0.0f;

    const float* Ap = A + (size_t)(m0 + lrow) * K;
    const bool bvalid = brow < DBLW;
    const float* Wp = W + (size_t)(bvalid ? brow : 0) * K;

    float4 ra0 = *(const float4*)(Ap + lc);
    float4 ra1 = *(const float4*)(Ap + lc + 4);
    float4 rb  = bvalid ? *(const float4*)(Wp + bc) : make_float4(0.f, 0.f, 0.f, 0.f);

    As[0][lc + 0][lrow] = ra0.x; As[0][lc + 1][lrow] = ra0.y;
    As[0][lc + 2][lrow] = ra0.z; As[0][lc + 3][lrow] = ra0.w;
    As[0][lc + 4][lrow] = ra1.x; As[0][lc + 5][lrow] = ra1.y;
    As[0][lc + 6][lrow] = ra1.z; As[0][lc + 7][lrow] = ra1.w;
    Bs[0][bc + 0][brow] = rb.x; Bs[0][bc + 1][brow] = rb.y;
    Bs[0][bc + 2][brow] = rb.z; Bs[0][bc + 3][brow] = rb.w;
    __syncthreads();

    const int nk = K / FBK;
    for (int it = 0; it < nk; it++) {
        const int cur = it & 1, nxt = cur ^ 1;
        if (it + 1 < nk) {
            const int kb = (it + 1) * FBK;
            ra0 = *(const float4*)(Ap + kb + lc);
            ra1 = *(const float4*)(Ap + kb + lc + 4);
            rb  = bvalid ? *(const float4*)(Wp + kb + bc) : make_float4(0.f, 0.f, 0.f, 0.f);
        }
        #pragma unroll
        for (int k = 0; k < FBK; k++) {
            float4 a0 = *(const float4*)&As[cur][k][ty * 4];
            float4 a1 = *(const float4*)&As[cur][k][ty * 4 + 64];
            float4 b0 = *(const float4*)&Bs[cur][k][tx * 4];
            float av[8] = {a0.x, a0.y, a0.z, a0.w, a1.x, a1.y, a1.z, a1.w};
            float bv[4] = {b0.x, b0.y, b0.z, b0.w};
            #pragma unroll
            for (int ii = 0; ii < 8; ii++)
                #pragma unroll
                for (int jj = 0; jj < 4; jj++)
                    acc[ii][jj] = fmaf(av[ii], bv[jj], acc[ii][jj]);
        }
        if (it + 1 < nk) {
            As[nxt][lc + 0][lrow] = ra0.x; As[nxt][lc + 1][lrow] = ra0.y;
            As[nxt][lc + 2][lrow] = ra0.z; As[nxt][lc + 3][lrow] = ra0.w;
            As[nxt][lc + 4][lrow] = ra1.x; As[nxt][lc + 5][lrow] = ra1.y;
            As[nxt][lc + 6][lrow] = ra1.z; As[nxt][lc + 7][lrow] = ra1.w;
            Bs[nxt][bc + 0][brow] = rb.x; Bs[nxt][bc + 1][brow] = rb.y;
            Bs[nxt][bc + 2][brow] = rb.z; Bs[nxt][bc + 3][brow] = rb.w;
        }
        __syncthreads();
    }

    #pragma unroll
    for (int ii = 0; ii < 8; ii++) {
        int r = m0 + ty * 4 + ((ii < 4) ? ii : 60 + ii);
        float* crow = C + (size_t)r * DBLW;
        #pragma unroll
        for (int jj = 0; jj < 4; jj++) {
            int c = tx * 4 + jj;
            if (c < DBLW) crow[c] = acc[ii][jj];
        }
    }
}

// ---------------- fp32 SGEMM BKK=8 (dtproj: K=24) ----------------
#define BM 128
#define BN 128
#define BKK 8

__global__ void __launch_bounds__(256)
sgemm_softplus(const float* __restrict__ A, const float* __restrict__ W,
               float* __restrict__ C, const float* __restrict__ bias,
               int M, int N, int K, int lda, int ldw, int ldc) {
    __shared__ float As[BKK][BM + 4];
    __shared__ float Bs[BKK][BN + 4];

    int m0 = blockIdx.y * BM;
    int n0 = blockIdx.x * BN;
    int tid = threadIdx.x;
    int lrow = tid >> 1;
    int lcol = (tid & 1) * 4;
    int tx = tid & 15, ty = tid >> 4;

    float acc[8][8];
    #pragma unroll
    for (int i = 0; i < 8; i++)
        #pragma unroll
        for (int j = 0; j < 8; j++) acc[i][j] = 0.0f;

    float4 ra = *(const float4*)(A + (size_t)(m0 + lrow) * lda + lcol);
    float4 rb;
    {
        int n = n0 + lrow;
        rb = (n < N) ? *(const float4*)(W + (size_t)n * ldw + lcol)
                     : make_float4(0.f, 0.f, 0.f, 0.f);
    }

    for (int k0 = 0; k0 < K; k0 += BKK) {
        As[lcol + 0][lrow] = ra.x;
        As[lcol + 1][lrow] = ra.y;
        As[lcol + 2][lrow] = ra.z;
        As[lcol + 3][lrow] = ra.w;
        Bs[lcol + 0][lrow] = rb.x;
        Bs[lcol + 1][lrow] = rb.y;
        Bs[lcol + 2][lrow] = rb.z;
        Bs[lcol + 3][lrow] = rb.w;
        __syncthreads();

        if (k0 + BKK < K) {
            ra = *(const float4*)(A + (size_t)(m0 + lrow) * lda + (k0 + BKK) + lcol);
            int n = n0 + lrow;
            rb = (n < N) ? *(const float4*)(W + (size_t)n * ldw + (k0 + BKK) + lcol)
                         : make_float4(0.f, 0.f, 0.f, 0.f);
        }

        #pragma unroll
        for (int k = 0; k < BKK; k++) {
            float4 a0 = *(const float4*)&As[k][ty * 4];
            float4 a1 = *(const float4*)&As[k][ty * 4 + 64];
            float4 b0 = *(const float4*)&Bs[k][tx * 4];
            float4 b1 = *(const float4*)&Bs[k][tx * 4 + 64];
            float av[8] = {a0.x, a0.y, a0.z, a0.w, a1.x, a1.y, a1.z, a1.w};
            float bv[8] = {b0.x, b0.y, b0.z, b0.w, b1.x, b1.y, b1.z, b1.w};
            #pragma unroll
            for (int ii = 0; ii < 8; ii++)
                #pragma unroll
                for (int jj = 0; jj < 8; jj++)
                    acc[ii][jj] = fmaf(av[ii], bv[jj], acc[ii][jj]);
        }
        __syncthreads();
    }

    #pragma unroll
    for (int ii = 0; ii < 8; ii++) {
        int r = m0 + ty * 4 + ((ii < 4) ? ii : 60 + ii);
        float* crow = C + (size_t)r * ldc;
        #pragma unroll
        for (int jj = 0; jj < 8; jj++) {
            int c = n0 + tx * 4 + ((jj < 4) ? jj : 60 + jj);
            if (c >= N) continue;
            crow[c] = softplusf(acc[ii][jj] + bias[c]);
        }
    }
}

// ---------------- causal depthwise conv (DCONV=4) + silu ----------------
// each thread: 4 consecutive tokens x 4 channels (register tap reuse)
__global__ void conv_silu_kernel(const float* __restrict__ xz, float* __restrict__ xi,
                                 const float* __restrict__ w, const float* __restrict__ cb) {
    const int nD4 = DINNER / 4;
    int idx = blockIdx.x * blockDim.x + threadIdx.x;
    if (idx >= (MTOK / 4) * nD4) return;
    int mg = idx / nD4;
    int d4 = (idx % nD4) * 4;
    int m0 = mg * 4;
    int l0 = m0 & (LSEQ - 1);

    float4 w0 = *(const float4*)(w + (d4 + 0) * NCONV);
    float4 w1 = *(const float4*)(w + (d4 + 1) * NCONV);
    float4 w2 = *(const float4*)(w + (d4 + 2) * NCONV);
    float4 w3 = *(const float4*)(w + (d4 + 3) * NCONV);
    float4 cbv = *(const float4*)(cb + d4);

    float4 v[7];
    const float* base = xz + (size_t)m0 * (2 * DINNER) + d4;
    #pragma unroll
    for (int j = 0; j < 7; j++) {
        int dl = l0 - 3 + j;
        v[j] = (dl >= 0) ? *(const float4*)(base + (size_t)(j - 3) * (2 * DINNER))
                         : make_float4(0.f, 0.f, 0.f, 0.f);
    }

    const float wk0[4] = {w0.x, w0.y, w0.z, w0.w};
    const float wk1[4] = {w1.x, w1.y, w1.z, w1.w};
    const float wk2[4] = {w2.x, w2.y, w2.z, w2.w};
    const float wk3[4] = {w3.x, w3.y, w3.z, w3.w};

    #pragma unroll
    for (int tt = 0; tt < 4; tt++) {
        float4 acc = cbv;
        #pragma unroll
        for (int k = 0; k < NCONV; k++) {
            float4 xv = v[tt + k];
            acc.x = fmaf(xv.x, wk0[k], acc.x);
            acc.y = fmaf(xv.y, wk1[k], acc.y);
            acc.z = fmaf(xv.z, wk2[k], acc.z);
            acc.w = fmaf(xv.w, wk3[k], acc.w);
        }
        acc.x = siluf(acc.x);
        acc.y = siluf(acc.y);
        acc.z = siluf(acc.z);
        acc.w = siluf(acc.w);
        *(float4*)(xi + (size_t)(m0 + tt) * DINNER + d4) = acc;
    }
}

// ---------------- selective scan (gating with silu(z) fused) ----------------
__global__ void __launch_bounds__(256)
scan_kernel(const float* __restrict__ xi, const float* __restrict__ dt,
            const float* __restrict__ dbl, const float* __restrict__ A_log,
            const float* __restrict__ Dp, const float* __restrict__ xz,
            float* __restrict__ y) {
    int b    = blockIdx.x;
    int dblk = blockIdx.y;
    int tid  = threadIdx.x;
    int dl   = tid >> 4;
    int s    = tid & 15;
    int d    = dblk * 16 + dl;

    float aL2 = -expf(A_log[d * NSTATE + s]) * 1.4426950408889634f;
    float Dd  = Dp[d];
    float h = 0.0f;

    const float* dt_p = dt + (size_t)b * LSEQ * DINNER + d;
    const float* u_p  = xi + (size_t)b * LSEQ * DINNER + d;
    const float* bc_p = dbl + (size_t)b * LSEQ * DBLW;
    const float* z_p  = xz + (size_t)b * LSEQ * (2 * DINNER) + DINNER + d;
    float*       y_p  = y  + (size_t)b * LSEQ * DINNER + d;

    #pragma unroll 4
    for (int t = 0; t < LSEQ; t++) {
        float dtv = dt_p[(size_t)t * DINNER];
        float uv  = u_p[(size_t)t * DINNER];
        float Bv  = bc_p[(size_t)t * DBLW + DTRANK + s];
        float Cv  = bc_p[(size_t)t * DBLW + DTRANK + NSTATE + s];
        float dA  = exp2f(dtv * aL2);
        h = fmaf(h, dA, (dtv * uv) * Bv);
        float p = h * Cv;
        p += __shfl_xor_sync(0xffffffffu, p, 8);
        p += __shfl_xor_sync(0xffffffffu, p, 4);
        p += __shfl_xor_sync(0xffffffffu, p, 2);
        p += __shfl_xor_sync(0xffffffffu, p, 1);
        if (s == 0) {
            float zv = z_p[(size_t)t * (2 * DINNER)];
            y_p[(size_t)t * DINNER] = fmaf(uv, Dd, p) * siluf(zv);
        }
    }
}

// ---------------- host launcher ----------------
static inline int cdiv(int a, int b) { return (a + b - 1) / b; }

extern "C" void kernel_launch(void* const* d_in, const int* in_sizes, int n_in,
                              void* d_out, int out_size) {
    const float* x_in     = (const float*)d_in[0];
    const float* pos      = (const float*)d_in[1];
    const float* ln1_s    = (const float*)d_in[2];
    const float* ln1_b    = (const float*)d_in[3];
    const float* in_w     = (const float*)d_in[4];
    const float* conv_w   = (const float*)d_in[5];
    const float* conv_b   = (const float*)d_in[6];
    const float* xproj_w  = (const float*)d_in[7];
    const float* dtproj_w = (const float*)d_in[8];
    const float* dtproj_b = (const float*)d_in[9];
    const float* A_log    = (const float*)d_in[10];
    const float* Dp       = (const float*)d_in[11];
    const float* out_w    = (const float*)d_in[12];
    const float* ff_ln_s  = (const float*)d_in[13];
    const float* ff_ln_b  = (const float*)d_in[14];
    const float* ff_w1    = (const float*)d_in[15];
    const float* ff_b1    = (const float*)d_in[16];
    const float* ff_w2    = (const float*)d_in[17];
    const float* ff_b2    = (const float*)d_in[18];
    const float* lno_s    = (const float*)d_in[19];
    const float* lno_b    = (const float*)d_in[20];

    float *bx, *bxn, *bxz, *bxi, *bdbl, *bdt, *by;
    cudaGetSymbolAddress((void**)&bx,   g_x);
    cudaGetSymbolAddress((void**)&bxn,  g_xn);
    cudaGetSymbolAddress((void**)&bxz,  g_xz);
    cudaGetSymbolAddress((void**)&bxi,  g_xi);
    cudaGetSymbolAddress((void**)&bdbl, g_dbl);
    cudaGetSymbolAddress((void**)&bdt,  g_dt);
    cudaGetSymbolAddress((void**)&by,   g_y);

    const int EW_BLK = 256;
    int ew_dim  = cdiv(MTOK * DIMC / 4, EW_BLK);
    int ew_conv = cdiv((MTOK / 4) * (DINNER / 4), EW_BLK);

    add_pos_kernel<<<ew_dim, EW_BLK>>>(x_in, pos, bx);

    for (int i = 0; i < NDEPTH; i++) {
        // ---- mamba block ----
        ln_kernel<<<MTOK / 8, 256>>>(bx, bxn, ln1_s + (size_t)i * DIMC, ln1_b + (size_t)i * DIMC);

        // xz = xn @ in_w^T  [M,1536]
        fgemm_tn<0><<<dim3((2 * DINNER) / FBN, MTOK / FBM), 256>>>(
            bxn, in_w + (size_t)i * 2 * DINNER * DIMC, bxz, nullptr,
            MTOK, 2 * DINNER, DIMC, DIMC, DIMC, 2 * DINNER);

        // xi = silu(conv1d(xz[:, :768]))
        conv_silu_kernel<<<ew_conv, EW_BLK>>>(
            bxz, bxi, conv_w + (size_t)i * DINNER * NCONV, conv_b + (size_t)i * DINNER);

        // dbl = xi @ xproj_w^T  [M,56]  (narrow BN=64 kernel)
        xgemm_tn<<<dim3(1, MTOK / FBM), 256>>>(
            bxi, xproj_w + (size_t)i * DBLW * DINNER, bdbl, MTOK, DINNER);

        // dt = softplus(dbl[:, :24] @ dtproj_w^T + dtproj_b)  [M,768]  (K=24)
        sgemm_softplus<<<dim3(cdiv(DINNER, BN), MTOK / BM), 256>>>(
            bdbl, dtproj_w + (size_t)i * DINNER * DTRANK, bdt,
            dtproj_b + (size_t)i * DINNER,
            MTOK, DINNER, DTRANK, DBLW, DTRANK, DINNER);

        // selective scan + gate -> y
        scan_kernel<<<dim3(BB, DINNER / 16), 256>>>(
            bxi, bdt, bdbl, A_log + (size_t)i * DINNER * NSTATE,
            Dp + (size_t)i * DINNER, bxz, by);

        // x += y @ out_w^T
        fgemm_tn<3><<<dim3(DIMC / FBN, MTOK / FBM), 256>>>(
            by, out_w + (size_t)i * DIMC * DINNER, bx, nullptr,
            MTOK, DIMC, DINNER, DINNER, DINNER, DIMC);

        // ---- feed-forward block ----
        ln_kernel<<<MTOK / 8, 256>>>(bx, bxn, ff_ln_s + (size_t)i * DIMC, ff_ln_b + (size_t)i * DIMC);

        // h = gelu(xn @ ff_w1^T + b1)
        fgemm_tn<2><<<dim3(HIDF / FBN, MTOK / FBM), 256>>>(
            bxn, ff_w1 + (size_t)i * HIDF * DIMC, by, ff_b1 + (size_t)i * HIDF,
            MTOK, HIDF, DIMC, DIMC, DIMC, HIDF);

        // x += h @ ff_w2^T + b2
        fgemm_tn<4><<<dim3(DIMC / FBN, MTOK / FBM), 256>>>(
            by, ff_w2 + (size_t)i * DIMC * HIDF, bx, ff_b2 + (size_t)i * DIMC,
            MTOK, DIMC, HIDF, HIDF, HIDF, DIMC);
    }

    ln_kernel<<<MTOK / 8, 256>>>(bx, (float*)d_out, lno_s, lno_b);
}

// round 13
// speedup vs baseline: 1.0143x; 1.0143x over previous
#include <cuda_runtime.h>
#include <math.h>
#include <stdint.h>

#define BB      8
#define LSEQ    4096
#define DIMC    384
#define NDEPTH  6
#define NSTATE  16
#define NCONV   4
#define DINNER  768
#define DTRANK  24
#define HIDF    768
#define MTOK    (BB*LSEQ)             // 32768
#define DBLW    (DTRANK + 2*NSTATE)   // 56

// ---------------- scratch (static device globals; no allocation) ----------------
__device__ float g_x  [MTOK*DIMC];
__device__ float g_xn [MTOK*DIMC];
__device__ float g_xz [MTOK*2*DINNER];
__device__ float g_xi [MTOK*DINNER];
__device__ float g_dbl[MTOK*DBLW];
__device__ float g_dt [MTOK*DINNER];
__device__ float g_y  [MTOK*DINNER];

// ---------------- math helpers ----------------
__device__ __forceinline__ float siluf(float v) {
    return v / (1.0f + expf(-v));
}
__device__ __forceinline__ float softplusf(float v) {
    return (v >= 0.0f) ? (v + log1pf(expf(-v))) : log1pf(expf(v));
}
__device__ __forceinline__ float geluf(float v) {
    float c = 0.7978845608028654f * (v + 0.044715f * v * v * v);
    return 0.5f * v * (1.0f + tanhf(c));
}

// ---------------- elementwise: x = x + pos_emb ----------------
__global__ void add_pos_kernel(const float* __restrict__ x,
                               const float* __restrict__ pos,
                               float* __restrict__ out) {
    int idx = blockIdx.x * blockDim.x + threadIdx.x;
    if (idx >= MTOK * DIMC / 4) return;
    int m  = idx / (DIMC / 4);
    int c4 = idx % (DIMC / 4);
    int l  = m & (LSEQ - 1);
    float4 xv = ((const float4*)x)[idx];
    float4 pv = ((const float4*)pos)[l * (DIMC / 4) + c4];
    xv.x += pv.x; xv.y += pv.y; xv.z += pv.z; xv.w += pv.w;
    ((float4*)out)[idx] = xv;
}

// ---------------- layernorm over DIMC=384 (one warp per token) ----------------
__global__ void ln_kernel(const float* __restrict__ x, float* __restrict__ o,
                          const float* __restrict__ s, const float* __restrict__ bb) {
    int gwarp = (blockIdx.x * blockDim.x + threadIdx.x) >> 5;
    int lane  = threadIdx.x & 31;
    if (gwarp >= MTOK) return;
    const float* xp = x + (size_t)gwarp * DIMC;
    float4 v0 = *(const float4*)(xp + lane * 4);
    float4 v1 = *(const float4*)(xp + 128 + lane * 4);
    float4 v2 = *(const float4*)(xp + 256 + lane * 4);
    float sum = v0.x + v0.y + v0.z + v0.w
              + v1.x + v1.y + v1.z + v1.w
              + v2.x + v2.y + v2.z + v2.w;
    #pragma unroll
    for (int off = 16; off >= 1; off >>= 1) sum += __shfl_xor_sync(0xffffffffu, sum, off);
    float mean = sum * (1.0f / DIMC);
    float q = 0.0f;
    #define QACC(t) { float d_ = (t) - mean; q = fmaf(d_, d_, q); }
    QACC(v0.x) QACC(v0.y) QACC(v0.z) QACC(v0.w)
    QACC(v1.x) QACC(v1.y) QACC(v1.z) QACC(v1.w)
    QACC(v2.x) QACC(v2.y) QACC(v2.z) QACC(v2.w)
    #undef QACC
    #pragma unroll
    for (int off = 16; off >= 1; off >>= 1) q += __shfl_xor_sync(0xffffffffu, q, off);
    float rstd = rsqrtf(q * (1.0f / DIMC) + 1e-5f);

    float4 s0 = *(const float4*)(s + lane * 4);
    float4 s1 = *(const float4*)(s + 128 + lane * 4);
    float4 s2 = *(const float4*)(s + 256 + lane * 4);
    float4 b0 = *(const float4*)(bb + lane * 4);
    float4 b1 = *(const float4*)(bb + 128 + lane * 4);
    float4 b2 = *(const float4*)(bb + 256 + lane * 4);
    float* op = o + (size_t)gwarp * DIMC;
    float4 r;
    r.x = (v0.x - mean) * rstd * s0.x + b0.x;
    r.y = (v0.y - mean) * rstd * s0.y + b0.y;
    r.z = (v0.z - mean) * rstd * s0.z + b0.z;
    r.w = (v0.w - mean) * rstd * s0.w + b0.w;
    *(float4*)(op + lane * 4) = r;
    r.x = (v1.x - mean) * rstd * s1.x + b1.x;
    r.y = (v1.y - mean) * rstd * s1.y + b1.y;
    r.z = (v1.z - mean) * rstd * s1.z + b1.z;
    r.w = (v1.w - mean) * rstd * s1.w + b1.w;
    *(float4*)(op + 128 + lane * 4) = r;
    r.x = (v2.x - mean) * rstd * s2.x + b2.x;
    r.y = (v2.y - mean) * rstd * s2.y + b2.y;
    r.z = (v2.z - mean) * rstd * s2.z + b2.z;
    r.w = (v2.w - mean) * rstd * s2.w + b2.w;
    *(float4*)(op + 256 + lane * 4) = r;
}

// ============================================================================
// fp32 FFMA TN GEMM, double-buffered smem, BK=16:
//   C[M,N] = A[M,K] @ W[N,K]^T
// Requires M%128==0, N%128==0, K%16==0 (in/out/ff1/ff2 all qualify).
// EPI: 0=store, 2=gelu(v+bias), 3=C+=v, 4=C+=v+bias
// ============================================================================
#define FBM 128
#define FBN 128
#define FBK 16

template <int EPI>
__global__ void __launch_bounds__(256)
fgemm_tn(const float* __restrict__ A, const float* __restrict__ W,
         float* __restrict__ C, const float* __restrict__ bias,
         int M, int N, int K, int lda, int ldw, int ldc) {
    __shared__ __align__(16) float As[2][FBK][FBM + 4];
    __shared__ __align__(16) float Bs[2][FBK][FBN + 4];

    const int m0 = blockIdx.y * FBM;
    const int n0 = blockIdx.x * FBN;
    const int tid = threadIdx.x;
    const int lrow = tid >> 1;          // 0..127
    const int lc   = (tid & 1) * 8;     // 0 or 8
    const int tx = tid & 15, ty = tid >> 4;

    float acc[8][8];
    #pragma unroll
    for (int i = 0; i < 8; i++)
        #pragma unroll
        for (int j = 0; j < 8; j++) acc[i][j] = 0.0f;

    const float* Ap = A + (size_t)(m0 + lrow) * lda;
    const float* Wp = W + (size_t)(n0 + lrow) * ldw;

    // preload tile 0 into registers then buffer 0
    float4 ra0 = *(const float4*)(Ap + lc);
    float4 ra1 = *(const float4*)(Ap + lc + 4);
    float4 rb0 = *(const float4*)(Wp + lc);
    float4 rb1 = *(const float4*)(Wp + lc + 4);

    As[0][lc + 0][lrow] = ra0.x; As[0][lc + 1][lrow] = ra0.y;
    As[0][lc + 2][lrow] = ra0.z; As[0][lc + 3][lrow] = ra0.w;
    As[0][lc + 4][lrow] = ra1.x; As[0][lc + 5][lrow] = ra1.y;
    As[0][lc + 6][lrow] = ra1.z; As[0][lc + 7][lrow] = ra1.w;
    Bs[0][lc + 0][lrow] = rb0.x; Bs[0][lc + 1][lrow] = rb0.y;
    Bs[0][lc + 2][lrow] = rb0.z; Bs[0][lc + 3][lrow] = rb0.w;
    Bs[0][lc + 4][lrow] = rb1.x; Bs[0][lc + 5][lrow] = rb1.y;
    Bs[0][lc + 6][lrow] = rb1.z; Bs[0][lc + 7][lrow] = rb1.w;
    __syncthreads();

    const int nk = K / FBK;
    for (int it = 0; it < nk; it++) {
        const int cur = it & 1, nxt = cur ^ 1;

        // prefetch next tile (global -> registers) while computing on cur
        if (it + 1 < nk) {
            const int kb = (it + 1) * FBK;
            ra0 = *(const float4*)(Ap + kb + lc);
            ra1 = *(const float4*)(Ap + kb + lc + 4);
            rb0 = *(const float4*)(Wp + kb + lc);
            rb1 = *(const float4*)(Wp + kb + lc + 4);
        }

        #pragma unroll
        for (int k = 0; k < FBK; k++) {
            float4 a0 = *(const float4*)&As[cur][k][ty * 4];
            float4 a1 = *(const float4*)&As[cur][k][ty * 4 + 64];
            float4 b0 = *(const float4*)&Bs[cur][k][tx * 4];
            float4 b1 = *(const float4*)&Bs[cur][k][tx * 4 + 64];
            float av[8] = {a0.x, a0.y, a0.z, a0.w, a1.x, a1.y, a1.z, a1.w};
            float bv[8] = {b0.x, b0.y, b0.z, b0.w, b1.x, b1.y, b1.z, b1.w};
            #pragma unroll
            for (int ii = 0; ii < 8; ii++)
                #pragma unroll
                for (int jj = 0; jj < 8; jj++)
                    acc[ii][jj] = fmaf(av[ii], bv[jj], acc[ii][jj]);
        }

        if (it + 1 < nk) {
            As[nxt][lc + 0][lrow] = ra0.x; As[nxt][lc + 1][lrow] = ra0.y;
            As[nxt][lc + 2][lrow] = ra0.z; As[nxt][lc + 3][lrow] = ra0.w;
            As[nxt][lc + 4][lrow] = ra1.x; As[nxt][lc + 5][lrow] = ra1.y;
            As[nxt][lc + 6][lrow] = ra1.z; As[nxt][lc + 7][lrow] = ra1.w;
            Bs[nxt][lc + 0][lrow] = rb0.x; Bs[nxt][lc + 1][lrow] = rb0.y;
            Bs[nxt][lc + 2][lrow] = rb0.z; Bs[nxt][lc + 3][lrow] = rb0.w;
            Bs[nxt][lc + 4][lrow] = rb1.x; Bs[nxt][lc + 5][lrow] = rb1.y;
            Bs[nxt][lc + 6][lrow] = rb1.z; Bs[nxt][lc + 7][lrow] = rb1.w;
        }
        __syncthreads();
    }

    // vectorized epilogue: rows ty*4+{0..3,64..67}, cols n0+tx*4+{0,64}
    #pragma unroll
    for (int ii = 0; ii < 8; ii++) {
        int r = m0 + ty * 4 + ((ii < 4) ? ii : 60 + ii);
        float* crow = C + (size_t)r * ldc;
        #pragma unroll
        for (int half = 0; half < 2; half++) {
            int c = n0 + tx * 4 + half * 64;
            float v0 = acc[ii][half * 4 + 0];
            float v1 = acc[ii][half * 4 + 1];
            float v2 = acc[ii][half * 4 + 2];
            float v3 = acc[ii][half * 4 + 3];
            float4 out;
            if (EPI == 0) {
                out = make_float4(v0, v1, v2, v3);
            } else if (EPI == 2) {
                const float4 bv = *(const float4*)(bias + c);
                out = make_float4(geluf(v0 + bv.x), geluf(v1 + bv.y),
                                  geluf(v2 + bv.z), geluf(v3 + bv.w));
            } else if (EPI == 3) {
                float4 cv = *(const float4*)(crow + c);
                out = make_float4(cv.x + v0, cv.y + v1, cv.z + v2, cv.w + v3);
            } else {
                const float4 bv = *(const float4*)(bias + c);
                float4 cv = *(const float4*)(crow + c);
                out = make_float4(cv.x + v0 + bv.x, cv.y + v1 + bv.y,
                                  cv.z + v2 + bv.z, cv.w + v3 + bv.w);
            }
            *(float4*)(crow + c) = out;
        }
    }
}

// NOTE: fragment layout => acc[ii][half*4+q] maps to column n0 + tx*4 + half*64 + q
// (inner loop consumes bv[] in that order: b0 = cols tx*4.., b1 = cols tx*4+64..)

// ============================================================================
// xproj GEMM: C[M,56] = A[M,768] @ W[56,768]^T — narrow BN=64 tile (single
// n-tile), BK=16 double-buffered, microtile 8x4.
// ============================================================================
__global__ void __launch_bounds__(256)
xgemm_tn(const float* __restrict__ A, const float* __restrict__ W,
         float* __restrict__ C, int M, int K) {
    __shared__ __align__(16) float As[2][FBK][FBM + 4];
    __shared__ __align__(16) float Bs[2][FBK][64 + 4];

    const int m0 = blockIdx.y * FBM;
    const int tid = threadIdx.x;
    const int lrow = tid >> 1;            // A staging: 0..127
    const int lc   = (tid & 1) * 8;
    const int brow = tid >> 2;            // B staging: 0..63
    const int bc   = (tid & 3) * 4;       // 0,4,8,12
    const int tx = tid & 15, ty = tid >> 4;

    float acc[8][4];
    #pragma unroll
    for (int i = 0; i < 8; i++)
        #pragma unroll
        for (int j = 0; j < 4; j++) acc[i][j] = 0.0f;

    const float* Ap = A + (size_t)(m0 + lrow) * K;
    const bool bvalid = brow < DBLW;
    const float* Wp = W + (size_t)(bvalid ? brow : 0) * K;

    float4 ra0 = *(const float4*)(Ap + lc);
    float4 ra1 = *(const float4*)(Ap + lc + 4);
    float4 rb  = bvalid ? *(const float4*)(Wp + bc) : make_float4(0.f, 0.f, 0.f, 0.f);

    As[0][lc + 0][lrow] = ra0.x; As[0][lc + 1][lrow] = ra0.y;
    As[0][lc + 2][lrow] = ra0.z; As[0][lc + 3][lrow] = ra0.w;
    As[0][lc + 4][lrow] = ra1.x; As[0][lc + 5][lrow] = ra1.y;
    As[0][lc + 6][lrow] = ra1.z; As[0][lc + 7][lrow] = ra1.w;
    Bs[0][bc + 0][brow] = rb.x; Bs[0][bc + 1][brow] = rb.y;
    Bs[0][bc + 2][brow] = rb.z; Bs[0][bc + 3][brow] = rb.w;
    __syncthreads();

    const int nk = K / FBK;
    for (int it = 0; it < nk; it++) {
        const int cur = it & 1, nxt = cur ^ 1;
        if (it + 1 < nk) {
            const int kb = (it + 1) * FBK;
            ra0 = *(const float4*)(Ap + kb + lc);
            ra1 = *(const float4*)(Ap + kb + lc + 4);
            rb  = bvalid ? *(const float4*)(Wp + kb + bc) : make_float4(0.f, 0.f, 0.f, 0.f);
        }
        #pragma unroll
        for (int k = 0; k < FBK; k++) {
            float4 a0 = *(const float4*)&As[cur][k][ty * 4];
            float4 a1 = *(const float4*)&As[cur][k][ty * 4 + 64];
            float4 b0 = *(const float4*)&Bs[cur][k][tx * 4];
            float av[8] = {a0.x, a0.y, a0.z, a0.w, a1.x, a1.y, a1.z, a1.w};
            float bv[4] = {b0.x, b0.y, b0.z, b0.w};
            #pragma unroll
            for (int ii = 0; ii < 8; ii++)
                #pragma unroll
                for (int jj = 0; jj < 4; jj++)
                    acc[ii][jj] = fmaf(av[ii], bv[jj], acc[ii][jj]);
        }
        if (it + 1 < nk) {
            As[nxt][lc + 0][lrow] = ra0.x; As[nxt][lc + 1][lrow] = ra0.y;
            As[nxt][lc + 2][lrow] = ra0.z; As[nxt][lc + 3][lrow] = ra0.w;
            As[nxt][lc + 4][lrow] = ra1.x; As[nxt][lc + 5][lrow] = ra1.y;
            As[nxt][lc + 6][lrow] = ra1.z; As[nxt][lc + 7][lrow] = ra1.w;
            Bs[nxt][bc + 0][brow] = rb.x; Bs[nxt][bc + 1][brow] = rb.y;
            Bs[nxt][bc + 2][brow] = rb.z; Bs[nxt][bc + 3][brow] = rb.w;
        }
        __syncthreads();
    }

    #pragma unroll
    for (int ii = 0; ii < 8; ii++) {
        int r = m0 + ty * 4 + ((ii < 4) ? ii : 60 + ii);
        float* crow = C + (size_t)r * DBLW;
        #pragma unroll
        for (int jj = 0; jj < 4; jj++) {
            int c = tx * 4 + jj;
            if (c < DBLW) crow[c] = acc[ii][jj];
        }
    }
}

// ---------------- fp32 SGEMM BKK=8 (dtproj: K=24) ----------------
#define BM 128
#define BN 128
#define BKK 8

__global__ void __launch_bounds__(256)
sgemm_softplus(const float* __restrict__ A, const float* __restrict__ W,
               float* __restrict__ C, const float* __restrict__ bias,
               int M, int N, int K, int lda, int ldw, int ldc) {
    __shared__ float As[BKK][BM + 4];
    __shared__ float Bs[BKK][BN + 4];

    int m0 = blockIdx.y * BM;
    int n0 = blockIdx.x * BN;
    int tid = threadIdx.x;
    int lrow = tid >> 1;
    int lcol = (tid & 1) * 4;
    int tx = tid & 15, ty = tid >> 4;

    float acc[8][8];
    #pragma unroll
    for (int i = 0; i < 8; i++)
        #pragma unroll
        for (int j = 0; j < 8; j++) acc[i][j] = 0.0f;

    float4 ra = *(const float4*)(A + (size_t)(m0 + lrow) * lda + lcol);
    float4 rb;
    {
        int n = n0 + lrow;
        rb = (n < N) ? *(const float4*)(W + (size_t)n * ldw + lcol)
                     : make_float4(0.f, 0.f, 0.f, 0.f);
    }

    for (int k0 = 0; k0 < K; k0 += BKK) {
        As[lcol + 0][lrow] = ra.x;
        As[lcol + 1][lrow] = ra.y;
        As[lcol + 2][lrow] = ra.z;
        As[lcol + 3][lrow] = ra.w;
        Bs[lcol + 0][lrow] = rb.x;
        Bs[lcol + 1][lrow] = rb.y;
        Bs[lcol + 2][lrow] = rb.z;
        Bs[lcol + 3][lrow] = rb.w;
        __syncthreads();

        if (k0 + BKK < K) {
            ra = *(const float4*)(A + (size_t)(m0 + lrow) * lda + (k0 + BKK) + lcol);
            int n = n0 + lrow;
            rb = (n < N) ? *(const float4*)(W + (size_t)n * ldw + (k0 + BKK) + lcol)
                         : make_float4(0.f, 0.f, 0.f, 0.f);
        }

        #pragma unroll
        for (int k = 0; k < BKK; k++) {
            float4 a0 = *(const float4*)&As[k][ty * 4];
            float4 a1 = *(const float4*)&As[k][ty * 4 + 64];
            float4 b0 = *(const float4*)&Bs[k][tx * 4];
            float4 b1 = *(const float4*)&Bs[k][tx * 4 + 64];
            float av[8] = {a0.x, a0.y, a0.z, a0.w, a1.x, a1.y, a1.z, a1.w};
            float bv[8] = {b0.x, b0.y, b0.z, b0.w, b1.x, b1.y, b1.z, b1.w};
            #pragma unroll
            for (int ii = 0; ii < 8; ii++)
                #pragma unroll
                for (int jj = 0; jj < 8; jj++)
                    acc[ii][jj] = fmaf(av[ii], bv[jj], acc[ii][jj]);
        }
        __syncthreads();
    }

    #pragma unroll
    for (int ii = 0; ii < 8; ii++) {
        int r = m0 + ty * 4 + ((ii < 4) ? ii : 60 + ii);
        float* crow = C + (size_t)r * ldc;
        #pragma unroll
        for (int jj = 0; jj < 8; jj++) {
            int c = n0 + tx * 4 + ((jj < 4) ? jj : 60 + jj);
            if (c >= N) continue;
            crow[c] = softplusf(acc[ii][jj] + bias[c]);
        }
    }
}

// ---------------- causal depthwise conv (DCONV=4) + silu ----------------
// each thread: 4 consecutive tokens x 4 channels (register tap reuse)
__global__ void conv_silu_kernel(const float* __restrict__ xz, float* __restrict__ xi,
                                 const float* __restrict__ w, const float* __restrict__ cb) {
    const int nD4 = DINNER / 4;
    int idx = blockIdx.x * blockDim.x + threadIdx.x;
    if (idx >= (MTOK / 4) * nD4) return;
    int mg = idx / nD4;
    int d4 = (idx % nD4) * 4;
    int m0 = mg * 4;
    int l0 = m0 & (LSEQ - 1);

    float4 w0 = *(const float4*)(w + (d4 + 0) * NCONV);
    float4 w1 = *(const float4*)(w + (d4 + 1) * NCONV);
    float4 w2 = *(const float4*)(w + (d4 + 2) * NCONV);
    float4 w3 = *(const float4*)(w + (d4 + 3) * NCONV);
    float4 cbv = *(const float4*)(cb + d4);

    float4 v[7];
    const float* base = xz + (size_t)m0 * (2 * DINNER) + d4;
    #pragma unroll
    for (int j = 0; j < 7; j++) {
        int dl = l0 - 3 + j;
        v[j] = (dl >= 0) ? *(const float4*)(base + (size_t)(j - 3) * (2 * DINNER))
                         : make_float4(0.f, 0.f, 0.f, 0.f);
    }

    const float wk0[4] = {w0.x, w0.y, w0.z, w0.w};
    const float wk1[4] = {w1.x, w1.y, w1.z, w1.w};
    const float wk2[4] = {w2.x, w2.y, w2.z, w2.w};
    const float wk3[4] = {w3.x, w3.y, w3.z, w3.w};

    #pragma unroll
    for (int tt = 0; tt < 4; tt++) {
        float4 acc = cbv;
        #pragma unroll
        for (int k = 0; k < NCONV; k++) {
            float4 xv = v[tt + k];
            acc.x = fmaf(xv.x, wk0[k], acc.x);
            acc.y = fmaf(xv.y, wk1[k], acc.y);
            acc.z = fmaf(xv.z, wk2[k], acc.z);
            acc.w = fmaf(xv.w, wk3[k], acc.w);
        }
        acc.x = siluf(acc.x);
        acc.y = siluf(acc.y);
        acc.z = siluf(acc.z);
        acc.w = siluf(acc.w);
        *(float4*)(xi + (size_t)(m0 + tt) * DINNER + d4) = acc;
    }
}

// ---------------- selective scan (gating with silu(z) fused) ----------------
__global__ void __launch_bounds__(256)
scan_kernel(const float* __restrict__ xi, const float* __restrict__ dt,
            const float* __restrict__ dbl, const float* __restrict__ A_log,
            const float* __restrict__ Dp, const float* __restrict__ xz,
            float* __restrict__ y) {
    int b    = blockIdx.x;
    int dblk = blockIdx.y;
    int tid  = threadIdx.x;
    int dl   = tid >> 4;
    int s    = tid & 15;
    int d    = dblk * 16 + dl;

    float aL2 = -expf(A_log[d * NSTATE + s]) * 1.4426950408889634f;
    float Dd  = Dp[d];
    float h = 0.0f;

    const float* dt_p = dt + (size_t)b * LSEQ * DINNER + d;
    const float* u_p  = xi + (size_t)b * LSEQ * DINNER + d;
    const float* bc_p = dbl + (size_t)b * LSEQ * DBLW;
    const float* z_p  = xz + (size_t)b * LSEQ * (2 * DINNER) + DINNER + d;
    float*       y_p  = y  + (size_t)b * LSEQ * DINNER + d;

    #pragma unroll 4
    for (int t = 0; t < LSEQ; t++) {
        float dtv = dt_p[(size_t)t * DINNER];
        float uv  = u_p[(size_t)t * DINNER];
        float Bv  = bc_p[(size_t)t * DBLW + DTRANK + s];
        float Cv  = bc_p[(size_t)t * DBLW + DTRANK + NSTATE + s];
        float dA  = exp2f(dtv * aL2);
        h = fmaf(h, dA, (dtv * uv) * Bv);
        float p = h * Cv;
        p += __shfl_xor_sync(0xffffffffu, p, 8);
        p += __shfl_xor_sync(0xffffffffu, p, 4);
        p += __shfl_xor_sync(0xffffffffu, p, 2);
        p += __shfl_xor_sync(0xffffffffu, p, 1);
        if (s == 0) {
            float zv = z_p[(size_t)t * (2 * DINNER)];
            y_p[(size_t)t * DINNER] = fmaf(uv, Dd, p) * siluf(zv);
        }
    }
}

// ---------------- host launcher ----------------
static inline int cdiv(int a, int b) { return (a + b - 1) / b; }

extern "C" void kernel_launch(void* const* d_in, const int* in_sizes, int n_in,
                              void* d_out, int out_size) {
    const float* x_in     = (const float*)d_in[0];
    const float* pos      = (const float*)d_in[1];
    const float* ln1_s    = (const float*)d_in[2];
    const float* ln1_b    = (const float*)d_in[3];
    const float* in_w     = (const float*)d_in[4];
    const float* conv_w   = (const float*)d_in[5];
    const float* conv_b   = (const float*)d_in[6];
    const float* xproj_w  = (const float*)d_in[7];
    const float* dtproj_w = (const float*)d_in[8];
    const float* dtproj_b = (const float*)d_in[9];
    const float* A_log    = (const float*)d_in[10];
    const float* Dp       = (const float*)d_in[11];
    const float* out_w    = (const float*)d_in[12];
    const float* ff_ln_s  = (const float*)d_in[13];
    const float* ff_ln_b  = (const float*)d_in[14];
    const float* ff_w1    = (const float*)d_in[15];
    const float* ff_b1    = (const float*)d_in[16];
    const float* ff_w2    = (const float*)d_in[17];
    const float* ff_b2    = (const float*)d_in[18];
    const float* lno_s    = (const float*)d_in[19];
    const float* lno_b    = (const float*)d_in[20];

    float *bx, *bxn, *bxz, *bxi, *bdbl, *bdt, *by;
    cudaGetSymbolAddress((void**)&bx,   g_x);
    cudaGetSymbolAddress((void**)&bxn,  g_xn);
    cudaGetSymbolAddress((void**)&bxz,  g_xz);
    cudaGetSymbolAddress((void**)&bxi,  g_xi);
    cudaGetSymbolAddress((void**)&bdbl, g_dbl);
    cudaGetSymbolAddress((void**)&bdt,  g_dt);
    cudaGetSymbolAddress((void**)&by,   g_y);

    const int EW_BLK = 256;
    int ew_dim  = cdiv(MTOK * DIMC / 4, EW_BLK);
    int ew_conv = cdiv((MTOK / 4) * (DINNER / 4), EW_BLK);

    add_pos_kernel<<<ew_dim, EW_BLK>>>(x_in, pos, bx);

    for (int i = 0; i < NDEPTH; i++) {
        // ---- mamba block ----
        ln_kernel<<<MTOK / 8, 256>>>(bx, bxn, ln1_s + (size_t)i * DIMC, ln1_b + (size_t)i * DIMC);

        // xz = xn @ in_w^T  [M,1536]
        fgemm_tn<0><<<dim3((2 * DINNER) / FBN, MTOK / FBM), 256>>>(
            bxn, in_w + (size_t)i * 2 * DINNER * DIMC, bxz, nullptr,
            MTOK, 2 * DINNER, DIMC, DIMC, DIMC, 2 * DINNER);

        // xi = silu(conv1d(xz[:, :768]))
        conv_silu_kernel<<<ew_conv, EW_BLK>>>(
            bxz, bxi, conv_w + (size_t)i * DINNER * NCONV, conv_b + (size_t)i * DINNER);

        // dbl = xi @ xproj_w^T  [M,56]  (narrow BN=64 kernel)
        xgemm_tn<<<dim3(1, MTOK / FBM), 256>>>(
            bxi, xproj_w + (size_t)i * DBLW * DINNER, bdbl, MTOK, DINNER);

        // dt = softplus(dbl[:, :24] @ dtproj_w^T + dtproj_b)  [M,768]  (K=24)
        sgemm_softplus<<<dim3(cdiv(DINNER, BN), MTOK / BM), 256>>>(
            bdbl, dtproj_w + (size_t)i * DINNER * DTRANK, bdt,
            dtproj_b + (size_t)i * DINNER,
            MTOK, DINNER, DTRANK, DBLW, DTRANK, DINNER);

        // selective scan + gate -> y
        scan_kernel<<<dim3(BB, DINNER / 16), 256>>>(
            bxi, bdt, bdbl, A_log + (size_t)i * DINNER * NSTATE,
            Dp + (size_t)i * DINNER, bxz, by);

        // x += y @ out_w^T
        fgemm_tn<3><<<dim3(DIMC / FBN, MTOK / FBM), 256>>>(
            by, out_w + (size_t)i * DIMC * DINNER, bx, nullptr,
            MTOK, DIMC, DINNER, DINNER, DINNER, DIMC);

        // ---- feed-forward block ----
        ln_kernel<<<MTOK / 8, 256>>>(bx, bxn, ff_ln_s + (size_t)i * DIMC, ff_ln_b + (size_t)i * DIMC);

        // h = gelu(xn @ ff_w1^T + b1)
        fgemm_tn<2><<<dim3(HIDF / FBN, MTOK / FBM), 256>>>(
            bxn, ff_w1 + (size_t)i * HIDF * DIMC, by, ff_b1 + (size_t)i * HIDF,
            MTOK, HIDF, DIMC, DIMC, DIMC, HIDF);

        // x += h @ ff_w2^T + b2
        fgemm_tn<4><<<dim3(DIMC / FBN, MTOK / FBM), 256>>>(
            by, ff_w2 + (size_t)i * DIMC * HIDF, bx, ff_b2 + (size_t)i * DIMC,
            MTOK, DIMC, HIDF, HIDF, HIDF, DIMC);
    }

    ln_kernel<<<MTOK / 8, 256>>>(bx, (float*)d_out, lno_s, lno_b);
}